// round 2
// baseline (speedup 1.0000x reference)
#include <cuda_runtime.h>

// MaxPool3d k=2 s=2 over fp32 [2,32,128,128,128] -> [2,32,64,64,64]
// Each thread: 4 outputs along W. Reads 8x float4 (2 w-chunks x 2 h x 2 d),
// writes 1x float4. 16 threads cover a full 512B input row; MLP=8.
// Streaming cache hints (read-once / write-once data).

#define W_IN    128
#define HW_IN   (128 * 128)
#define DHW_IN  (128 * 128 * 128)
#define W_OUT   64
#define HW_OUT  (64 * 64)
#define DHW_OUT (64 * 64 * 64)

__global__ void __launch_bounds__(256) maxpool3d_k2s2_v2(
    const float* __restrict__ in, float* __restrict__ out, int n_quads)
{
    int tid = blockIdx.x * blockDim.x + threadIdx.x;
    if (tid >= n_quads) return;

    // tid -> (bc, d, h, q) : q in [0,16) -> outputs w = 4q..4q+3
    int q  = tid & 15;
    int t1 = tid >> 4;
    int h  = t1 & 63;
    int t2 = t1 >> 6;
    int d  = t2 & 63;
    int bc = t2 >> 6;            // 0..63

    const float4* base = reinterpret_cast<const float4*>(
        in + (size_t)bc * DHW_IN + (size_t)(2 * d) * HW_IN + (size_t)(2 * h) * W_IN)
        + 2 * q;

    // 8 independent loads: rows (2d,2h),(2d,2h+1),(2d+1,2h),(2d+1,2h+1) x 2 chunks
    float4 r0a = __ldcs(base);
    float4 r0b = __ldcs(base + 1);
    float4 r1a = __ldcs(base + (W_IN / 4));
    float4 r1b = __ldcs(base + (W_IN / 4) + 1);
    float4 r2a = __ldcs(base + (HW_IN / 4));
    float4 r2b = __ldcs(base + (HW_IN / 4) + 1);
    float4 r3a = __ldcs(base + (HW_IN / 4 + W_IN / 4));
    float4 r3b = __ldcs(base + (HW_IN / 4 + W_IN / 4) + 1);

    float4 res;
    res.x = fmaxf(fmaxf(fmaxf(r0a.x, r0a.y), fmaxf(r1a.x, r1a.y)),
                  fmaxf(fmaxf(r2a.x, r2a.y), fmaxf(r3a.x, r3a.y)));
    res.y = fmaxf(fmaxf(fmaxf(r0a.z, r0a.w), fmaxf(r1a.z, r1a.w)),
                  fmaxf(fmaxf(r2a.z, r2a.w), fmaxf(r3a.z, r3a.w)));
    res.z = fmaxf(fmaxf(fmaxf(r0b.x, r0b.y), fmaxf(r1b.x, r1b.y)),
                  fmaxf(fmaxf(r2b.x, r2b.y), fmaxf(r3b.x, r3b.y)));
    res.w = fmaxf(fmaxf(fmaxf(r0b.z, r0b.w), fmaxf(r1b.z, r1b.w)),
                  fmaxf(fmaxf(r2b.z, r2b.w), fmaxf(r3b.z, r3b.w)));

    float4* op = reinterpret_cast<float4*>(
        out + (size_t)bc * DHW_OUT + (size_t)d * HW_OUT + (size_t)h * W_OUT) + q;
    __stcs(op, res);
}

extern "C" void kernel_launch(void* const* d_in, const int* in_sizes, int n_in,
                              void* d_out, int out_size)
{
    const float* in = (const float*)d_in[0];
    float* out = (float*)d_out;
    int n_quads = out_size / 4;              // 4,194,304
    int threads = 256;
    int blocks = (n_quads + threads - 1) / threads;
    maxpool3d_k2s2_v2<<<blocks, threads>>>(in, out, n_quads);
}